// round 3
// baseline (speedup 1.0000x reference)
#include <cuda_runtime.h>

// out[i] = (a^2 - 2*pi^2) * sin(pi*x0) * sin(pi*x1)   (P=1)
// N = 16777216 rows; input [N,2] fp32 row-major; out [N,1] fp32.
// HBM-bound: 128MB read + 64MB write. Each thread handles 4 rows:
// two independent float4 loads (MLP=2) -> one float4 store.

__global__ void __launch_bounds__(256)
helm_kernel(const float4* __restrict__ in,
            const float*  __restrict__ a,
            float4* __restrict__ out,
            int n_chunks)   // number of 4-row chunks
{
    const float pi = 3.14159265358979323846f;
    int i = blockIdx.x * blockDim.x + threadIdx.x;
    if (i >= n_chunks) return;

    // Two independent 16B loads, issued back-to-back (MLP=2)
    float4 v0 = in[2 * i];
    float4 v1 = in[2 * i + 1];

    float av = a[0];                       // broadcast, L1-resident
    float coef = fmaf(av, av, -2.0f * pi * pi);

    float4 r;
    r.x = coef * (sinf(pi * v0.x) * sinf(pi * v0.y));
    r.y = coef * (sinf(pi * v0.z) * sinf(pi * v0.w));
    r.z = coef * (sinf(pi * v1.x) * sinf(pi * v1.y));
    r.w = coef * (sinf(pi * v1.z) * sinf(pi * v1.w));

    out[i] = r;
}

extern "C" void kernel_launch(void* const* d_in, const int* in_sizes, int n_in,
                              void* d_out, int out_size)
{
    const float4* in = (const float4*)d_in[0];   // [N,2] fp32
    const float*  a  = (const float*)d_in[1];    // [1] fp32
    float4* out = (float4*)d_out;                // [N] fp32 viewed as N/4 float4

    int n_rows = out_size;          // N = 16777216 (divisible by 4)
    int n_chunks = n_rows / 4;      // 4 rows per thread

    int block = 256;
    int grid = (n_chunks + block - 1) / block;
    helm_kernel<<<grid, block>>>(in, a, out, n_chunks);
}

// round 5
// speedup vs baseline: 1.1954x; 1.1954x over previous
#include <cuda_runtime.h>

// out[i] = (a^2 - 2*pi^2) * __sinf(pi*x0) * __sinf(pi*x1)   (P=1)
// N = 16777216 rows; input [N,2] fp32; out [N,1] fp32.
// HBM-bound: 128MB read + 64MB write. Floor ~24-27us.
// Each thread: 8 rows = 4 independent float4 loads (MLP=4), 2 float4 stores.
// MUFU.SIN replaces software sinf -> kernel goes from issue-bound to DRAM-bound.

__global__ void __launch_bounds__(256)
helm_kernel(const float4* __restrict__ in,
            const float*  __restrict__ a,
            float4* __restrict__ out,
            int n_chunks)   // number of 8-row chunks
{
    const float pi = 3.14159265358979323846f;
    int i = blockIdx.x * blockDim.x + threadIdx.x;
    if (i >= n_chunks) return;

    float av = a[0];                       // broadcast, L1-resident; off critical path

    // Four independent 16B loads, front-batched (MLP=4)
    float4 v0 = in[4 * i + 0];
    float4 v1 = in[4 * i + 1];
    float4 v2 = in[4 * i + 2];
    float4 v3 = in[4 * i + 3];

    float coef = fmaf(av, av, -2.0f * pi * pi);

    float4 r0, r1;
    r0.x = coef * (__sinf(pi * v0.x) * __sinf(pi * v0.y));
    r0.y = coef * (__sinf(pi * v0.z) * __sinf(pi * v0.w));
    r0.z = coef * (__sinf(pi * v1.x) * __sinf(pi * v1.y));
    r0.w = coef * (__sinf(pi * v1.z) * __sinf(pi * v1.w));
    r1.x = coef * (__sinf(pi * v2.x) * __sinf(pi * v2.y));
    r1.y = coef * (__sinf(pi * v2.z) * __sinf(pi * v2.w));
    r1.z = coef * (__sinf(pi * v3.x) * __sinf(pi * v3.y));
    r1.w = coef * (__sinf(pi * v3.z) * __sinf(pi * v3.w));

    out[2 * i + 0] = r0;
    out[2 * i + 1] = r1;
}

extern "C" void kernel_launch(void* const* d_in, const int* in_sizes, int n_in,
                              void* d_out, int out_size)
{
    const float4* in = (const float4*)d_in[0];   // [N,2] fp32
    const float*  a  = (const float*)d_in[1];    // [1] fp32
    float4* out = (float4*)d_out;                // [N] fp32

    int n_rows = out_size;          // N = 16777216 (divisible by 8)
    int n_chunks = n_rows / 8;      // 8 rows per thread

    int block = 256;
    int grid = (n_chunks + block - 1) / block;   // 8192 blocks
    helm_kernel<<<grid, block>>>(in, a, out, n_chunks);
}